// round 1
// baseline (speedup 1.0000x reference)
#include <cuda_runtime.h>
#include <cstdint>

// Problem constants (fixed by the dataset shapes)
#define M_DIM 8192     // 4 * 2048
#define K_DIM 4096
#define N_DIM 11008
#define NZ_DIM 1376    // N_DIM / 8 packed qzeros cols
#define GS 128         // groupsize

// Tile config
#define BM 128
#define BN 128
#define BK 32
#define AST 36         // A smem row stride (floats): BK + 4 pad -> conflict-free frags
#define BST 136        // B smem row stride (floats): BN + 8 pad -> conflict-free frags
#define NSTAGES (K_DIM / BK)   // 128

#define SMEM_FLOATS (2 * BM * AST + 2 * BK * BST)
#define SMEM_BYTES (SMEM_FLOATS * 4)   // 71680 B

__device__ __forceinline__ uint32_t f2tf32(float f) {
    uint32_t r;
    asm("cvt.rna.tf32.f32 %0, %1;" : "=r"(r) : "f"(f));
    return r;
}

__device__ __forceinline__ void cp_async16(float* smem_dst, const float* gmem_src) {
    uint32_t s = (uint32_t)__cvta_generic_to_shared(smem_dst);
    asm volatile("cp.async.ca.shared.global [%0], [%1], 16;" :: "r"(s), "l"(gmem_src));
}
__device__ __forceinline__ void cp_commit() { asm volatile("cp.async.commit_group;" ::: "memory"); }
__device__ __forceinline__ void cp_wait0()  { asm volatile("cp.async.wait_group 0;" ::: "memory"); }

extern "C" __global__ void __launch_bounds__(256, 2)
qlinear_tf32_kernel(const float* __restrict__ x,
                    const uint32_t* __restrict__ qweight,
                    const float* __restrict__ scales,
                    const uint32_t* __restrict__ qzeros,
                    float* __restrict__ out)
{
    extern __shared__ float smem[];
    float* As = smem;                    // [2][BM][AST]
    float* Bs = smem + 2 * BM * AST;     // [2][BK][BST]

    const int t    = threadIdx.x;
    const int n0   = blockIdx.x * BN;
    const int m0   = blockIdx.y * BM;
    const int warp = t >> 5;
    const int lane = t & 31;
    const int g8   = lane >> 2;   // groupID (0..7)
    const int tg   = lane & 3;    // threadID in group
    const int warp_m = warp >> 2; // 0..1 (64 rows each)
    const int warp_n = warp & 3;  // 0..3 (32 cols each)

    float c[4][4][4];
    #pragma unroll
    for (int i = 0; i < 4; i++)
        #pragma unroll
        for (int j = 0; j < 4; j++)
            #pragma unroll
            for (int k = 0; k < 4; k++) c[i][j][k] = 0.f;

    // B-stage registers: 2 packed int32 per thread per stage
    uint32_t qv[2]; float sv[2]; float zv[2];

    // ---- stage loaders ----
    auto load_stage_A = [&](int s, int buf) {
        const float* xbase = x + (size_t)m0 * K_DIM + s * BK;
        float* dst = As + buf * BM * AST;
        #pragma unroll
        for (int i = 0; i < 4; i++) {
            int idx = t + i * 256;        // 0..1023
            int r   = idx >> 3;           // row 0..127
            int c4  = (idx & 7) * 4;      // col 0..28 step 4
            cp_async16(dst + r * AST + c4, xbase + (size_t)r * K_DIM + c4);
        }
    };

    auto load_stage_B = [&](int s) {
        int kp0 = s * (BK / 8);           // packed row base
        int grp = (s * BK) / GS;          // constant within a stage (32 | 128)
        #pragma unroll
        for (int i = 0; i < 2; i++) {
            int idx = t + i * 256;        // 0..511
            int kpl = idx >> 7;           // 0..3
            int n   = idx & 127;
            qv[i] = qweight[(size_t)(kp0 + kpl) * N_DIM + n0 + n];
            sv[i] = scales[(size_t)grp * N_DIM + n0 + n];
            uint32_t zq = qzeros[(size_t)grp * NZ_DIM + ((n0 + n) >> 3)];
            zv[i] = (float)((zq >> ((n & 7) * 4)) & 0xF);
        }
    };

    auto store_stage_B = [&](int buf) {
        float* dst = Bs + buf * BK * BST;
        #pragma unroll
        for (int i = 0; i < 2; i++) {
            int idx = t + i * 256;
            int kpl = idx >> 7;
            int n   = idx & 127;
            float s  = sv[i];
            float sz = s * zv[i];
            uint32_t q = qv[i];
            #pragma unroll
            for (int j = 0; j < 8; j++) {
                float w = fmaf(s, (float)((q >> (4 * j)) & 0xF), -sz);
                dst[(kpl * 8 + j) * BST + n] = w;
            }
        }
    };

    auto compute = [&](int buf) {
        const float* A = As + buf * BM * AST;
        const float* B = Bs + buf * BK * BST;
        #pragma unroll
        for (int kk = 0; kk < BK; kk += 8) {
            uint32_t af[4][4];
            #pragma unroll
            for (int mi = 0; mi < 4; mi++) {
                int row = warp_m * 64 + mi * 16 + g8;
                const float* ap = A + row * AST + kk + tg;
                af[mi][0] = f2tf32(ap[0]);
                af[mi][1] = f2tf32(ap[8 * AST]);
                af[mi][2] = f2tf32(ap[4]);
                af[mi][3] = f2tf32(ap[8 * AST + 4]);
            }
            uint32_t bf[4][2];
            #pragma unroll
            for (int ni = 0; ni < 4; ni++) {
                int col = warp_n * 32 + ni * 8 + g8;
                const float* bp = B + (kk + tg) * BST + col;
                bf[ni][0] = f2tf32(bp[0]);
                bf[ni][1] = f2tf32(bp[4 * BST]);
            }
            #pragma unroll
            for (int mi = 0; mi < 4; mi++)
                #pragma unroll
                for (int ni = 0; ni < 4; ni++) {
                    asm volatile(
                        "mma.sync.aligned.m16n8k8.row.col.f32.tf32.tf32.f32 "
                        "{%0,%1,%2,%3}, {%4,%5,%6,%7}, {%8,%9}, {%0,%1,%2,%3};"
                        : "+f"(c[mi][ni][0]), "+f"(c[mi][ni][1]),
                          "+f"(c[mi][ni][2]), "+f"(c[mi][ni][3])
                        : "r"(af[mi][0]), "r"(af[mi][1]), "r"(af[mi][2]), "r"(af[mi][3]),
                          "r"(bf[ni][0]), "r"(bf[ni][1]));
                }
        }
    };

    // ---- prologue ----
    load_stage_A(0, 0);
    cp_commit();
    load_stage_B(0);
    cp_wait0();
    store_stage_B(0);
    __syncthreads();

    // ---- mainloop ----
    for (int s = 0; s < NSTAGES; s++) {
        int buf = s & 1;
        if (s + 1 < NSTAGES) {
            load_stage_A(s + 1, buf ^ 1);
            cp_commit();
            load_stage_B(s + 1);
        }
        compute(buf);
        if (s + 1 < NSTAGES) {
            cp_wait0();
            store_stage_B(buf ^ 1);
        }
        __syncthreads();
    }

    // ---- epilogue ----
    #pragma unroll
    for (int mi = 0; mi < 4; mi++) {
        int row = m0 + warp_m * 64 + mi * 16 + g8;
        #pragma unroll
        for (int ni = 0; ni < 4; ni++) {
            int col = n0 + warp_n * 32 + ni * 8 + 2 * tg;
            float2 v0 = make_float2(c[mi][ni][0], c[mi][ni][1]);
            float2 v1 = make_float2(c[mi][ni][2], c[mi][ni][3]);
            *(float2*)(out + (size_t)row * N_DIM + col)       = v0;
            *(float2*)(out + (size_t)(row + 8) * N_DIM + col) = v1;
        }
    }
}

extern "C" void kernel_launch(void* const* d_in, const int* in_sizes, int n_in,
                              void* d_out, int out_size)
{
    const float*    x       = (const float*)d_in[0];
    const uint32_t* qweight = (const uint32_t*)d_in[1];
    const float*    scales  = (const float*)d_in[2];
    const uint32_t* qzeros  = (const uint32_t*)d_in[3];
    float*          out     = (float*)d_out;

    // Idempotent, host-side, capture-safe.
    cudaFuncSetAttribute(qlinear_tf32_kernel,
                         cudaFuncAttributeMaxDynamicSharedMemorySize, SMEM_BYTES);

    dim3 grid(N_DIM / BN, M_DIM / BM);   // x over N -> A tile-row reuse in L2 per wave
    qlinear_tf32_kernel<<<grid, 256, SMEM_BYTES>>>(x, qweight, scales, qzeros, out);
}

// round 4
// speedup vs baseline: 1.2605x; 1.2605x over previous
#include <cuda_runtime.h>
#include <cstdint>

// ---------------- problem constants ----------------
#define M_DIM 8192
#define K_DIM 4096
#define N_DIM 11008
#define NZ_DIM 1376          // N/8 packed qzeros cols
#define GS 128

// ---------------- GEMM tile config ----------------
#define BM 128
#define BN 256
#define BK 32                 // 32 tf32 -> 128 bytes per SMEM row (SW128 atom width)
#define NSTAGES (K_DIM / BK)  // 128
#define SPIPE 3

#define A_STAGE_BYTES (BM * 128)   // 16384
#define B_STAGE_BYTES (BN * 128)   // 32768
#define STAGE_BYTES (A_STAGE_BYTES + B_STAGE_BYTES)
#define SMEM_TOTAL (SPIPE * STAGE_BYTES)   // 147456 B

// ---------------- scratch (device globals: sanctioned scratch) ----------------
__device__ float g_wt[(size_t)N_DIM * K_DIM];   // dequantized W^T, tf32-rounded: [N, K]
__device__ float g_ax[(size_t)M_DIM * K_DIM];   // x rounded to tf32: [M, K]

// ---------------- helpers ----------------
__device__ __forceinline__ uint32_t f2tf32(float f) {
    uint32_t r; asm("cvt.rna.tf32.f32 %0, %1;" : "=r"(r) : "f"(f)); return r;
}
__device__ __forceinline__ void cp16(uint32_t saddr, const float* g) {
    asm volatile("cp.async.cg.shared.global [%0], [%1], 16;" :: "r"(saddr), "l"(g));
}
__device__ __forceinline__ void cp_commit() { asm volatile("cp.async.commit_group;" ::: "memory"); }
__device__ __forceinline__ void cp_wait2()  { asm volatile("cp.async.wait_group 2;" ::: "memory"); }
__device__ __forceinline__ uint32_t smem_u32(const void* p) {
    uint32_t a;
    asm("{ .reg .u64 t; cvta.to.shared.u64 t, %1; cvt.u32.u64 %0, t; }" : "=r"(a) : "l"(p));
    return a;
}

// ---------------- prep: round x to tf32 ----------------
extern "C" __global__ void round_a_kernel(const float4* __restrict__ x) {
    size_t i = (size_t)blockIdx.x * blockDim.x + threadIdx.x;
    float4 v = x[i];
    float4 r;
    r.x = __uint_as_float(f2tf32(v.x));
    r.y = __uint_as_float(f2tf32(v.y));
    r.z = __uint_as_float(f2tf32(v.z));
    r.w = __uint_as_float(f2tf32(v.w));
    ((float4*)g_ax)[i] = r;
}

// ---------------- prep: dequant + transpose W -> tf32 [N, K] ----------------
extern "C" __global__ void dequant_wt_kernel(const uint32_t* __restrict__ qweight,
                                             const float* __restrict__ scales,
                                             const uint32_t* __restrict__ qzeros) {
    int n  = blockIdx.x * blockDim.x + threadIdx.x;   // 0..11007
    int kp = blockIdx.y;                              // 0..511 packed k-row (8 k each)
    int g  = kp >> 4;                                 // group index
    uint32_t q  = qweight[(size_t)kp * N_DIM + n];
    float    s  = scales[(size_t)g * N_DIM + n];
    uint32_t zq = qzeros[(size_t)g * NZ_DIM + (n >> 3)];
    float    sz = s * (float)((zq >> ((n & 7) * 4)) & 0xF);
    float w[8];
    #pragma unroll
    for (int j = 0; j < 8; j++)
        w[j] = __uint_as_float(f2tf32(fmaf(s, (float)((q >> (4 * j)) & 0xF), -sz)));
    float4* dst = (float4*)(g_wt + (size_t)n * K_DIM + kp * 8);
    dst[0] = make_float4(w[0], w[1], w[2], w[3]);
    dst[1] = make_float4(w[4], w[5], w[6], w[7]);
}

// ---------------- main GEMM: dense tf32 mma.sync, 128x256 CTA, 64x64 warp ----------------
extern "C" __global__ void __launch_bounds__(256, 1)
qgemm_tf32(float* __restrict__ out) {
    extern __shared__ char smem[];
    uint32_t sb = smem_u32(smem);

    const int t = threadIdx.x;
    const int warp = t >> 5, lane = t & 31;
    const int g8 = lane >> 2, tg = lane & 3;
    const int warp_m = warp >> 2;    // 0..1  -> 64 rows
    const int warp_n = warp & 3;     // 0..3  -> 64 cols
    const int n0 = blockIdx.x * BN, m0 = blockIdx.y * BM;

    float c[4][8][4];
    #pragma unroll
    for (int i = 0; i < 4; i++)
        #pragma unroll
        for (int j = 0; j < 8; j++)
            #pragma unroll
            for (int k = 0; k < 4; k++) c[i][j][k] = 0.f;

    // ---- cp.async address precompute (SW128 swizzle on 128B rows) ----
    // A granules: 4 per thread; B granules: 8 per thread.
    const float* a_g[4]; uint32_t a_s[4];
    #pragma unroll
    for (int i = 0; i < 4; i++) {
        int idx = t + i * 256;            // 0..1023
        int r = idx >> 3, g = idx & 7;    // row 0..127, 16B granule 0..7
        a_g[i] = g_ax + (size_t)(m0 + r) * K_DIM + g * 4;
        a_s[i] = sb + r * 128 + ((g ^ (r & 7)) << 4);
    }
    const float* b_g[8]; uint32_t b_s[8];
    #pragma unroll
    for (int i = 0; i < 8; i++) {
        int idx = t + i * 256;            // 0..2047
        int r = idx >> 3, g = idx & 7;    // row 0..255
        b_g[i] = g_wt + (size_t)(n0 + r) * K_DIM + g * 4;
        b_s[i] = sb + A_STAGE_BYTES + r * 128 + ((g ^ (r & 7)) << 4);
    }

    auto fill = [&](int s) {
        int off = (s % SPIPE) * STAGE_BYTES;
        #pragma unroll
        for (int i = 0; i < 4; i++) cp16(a_s[i] + off, a_g[i] + s * BK);
        #pragma unroll
        for (int i = 0; i < 8; i++) cp16(b_s[i] + off, b_g[i] + s * BK);
        cp_commit();
    };

    fill(0); fill(1);

    // fragment smem element indexing (element units, swizzle: col k -> k ^ (row&7)<<2)
    const int axor = g8 << 2;             // row&7 == g8 for all fragment rows

    for (int s = 0; s < NSTAGES; s++) {
        if (s + 2 < NSTAGES) fill(s + 2); else cp_commit();
        cp_wait2();
        __syncthreads();

        const uint32_t* A = (const uint32_t*)(smem + (s % SPIPE) * STAGE_BYTES);
        const uint32_t* B = A + A_STAGE_BYTES / 4;

        #pragma unroll
        for (int kk = 0; kk < BK; kk += 8) {
            uint32_t af[4][4];
            #pragma unroll
            for (int mi = 0; mi < 4; mi++) {
                int r = warp_m * 64 + mi * 16 + g8;
                const uint32_t* ap = A + r * 32;
                af[mi][0] = ap[(kk + tg) ^ axor];
                af[mi][1] = ap[8 * 32 + ((kk + tg) ^ axor)];
                af[mi][2] = ap[(kk + 4 + tg) ^ axor];
                af[mi][3] = ap[8 * 32 + ((kk + 4 + tg) ^ axor)];
            }
            uint32_t bf[8][2];
            #pragma unroll
            for (int ni = 0; ni < 8; ni++) {
                int r = warp_n * 64 + ni * 8 + g8;
                const uint32_t* bp = B + r * 32;
                bf[ni][0] = bp[(kk + tg) ^ axor];
                bf[ni][1] = bp[(kk + 4 + tg) ^ axor];
            }
            #pragma unroll
            for (int mi = 0; mi < 4; mi++)
                #pragma unroll
                for (int ni = 0; ni < 8; ni++) {
                    asm volatile(
                        "mma.sync.aligned.m16n8k8.row.col.f32.tf32.tf32.f32 "
                        "{%0,%1,%2,%3}, {%4,%5,%6,%7}, {%8,%9}, {%0,%1,%2,%3};"
                        : "+f"(c[mi][ni][0]), "+f"(c[mi][ni][1]),
                          "+f"(c[mi][ni][2]), "+f"(c[mi][ni][3])
                        : "r"(af[mi][0]), "r"(af[mi][1]), "r"(af[mi][2]), "r"(af[mi][3]),
                          "r"(bf[ni][0]), "r"(bf[ni][1]));
                }
        }
        __syncthreads();
    }

    // ---- epilogue ----
    #pragma unroll
    for (int mi = 0; mi < 4; mi++) {
        int row = m0 + warp_m * 64 + mi * 16 + g8;
        float* o0 = out + (size_t)row * N_DIM;
        float* o1 = out + (size_t)(row + 8) * N_DIM;
        #pragma unroll
        for (int ni = 0; ni < 8; ni++) {
            int col = n0 + warp_n * 64 + ni * 8 + 2 * tg;
            *(float2*)(o0 + col) = make_float2(c[mi][ni][0], c[mi][ni][1]);
            *(float2*)(o1 + col) = make_float2(c[mi][ni][2], c[mi][ni][3]);
        }
    }
}

// ---------------- launch ----------------
extern "C" void kernel_launch(void* const* d_in, const int* in_sizes, int n_in,
                              void* d_out, int out_size) {
    const float*    x       = (const float*)d_in[0];
    const uint32_t* qweight = (const uint32_t*)d_in[1];
    const float*    scales  = (const float*)d_in[2];
    const uint32_t* qzeros  = (const uint32_t*)d_in[3];
    float*          out     = (float*)d_out;

    cudaFuncSetAttribute(qgemm_tf32,
                         cudaFuncAttributeMaxDynamicSharedMemorySize, SMEM_TOTAL);

    round_a_kernel<<<(unsigned)((size_t)M_DIM * K_DIM / 4 / 256), 256>>>((const float4*)x);
    dim3 dq_grid(N_DIM / 256, K_DIM / 8);   // (43, 512)
    dequant_wt_kernel<<<dq_grid, 256>>>(qweight, scales, qzeros);
    dim3 grid(N_DIM / BN, M_DIM / BM);      // (43, 64)
    qgemm_tf32<<<grid, 256, SMEM_TOTAL>>>(out);
}

// round 5
// speedup vs baseline: 1.3734x; 1.0896x over previous
#include <cuda_runtime.h>
#include <cstdint>

// ---------------- problem constants ----------------
#define M_DIM 8192
#define K_DIM 4096
#define N_DIM 11008
#define NZ_DIM 1376          // N/8 packed qzeros cols
#define GS 128

// ---------------- GEMM tile config ----------------
#define BM 128
#define BN 256
#define BK 32                 // 32 tf32 -> 128 bytes per SMEM row (SW128 atom width)
#define NSTAGES (K_DIM / BK)  // 128
#define SPIPE 4               // (s+3)%4 != s%4 -> single barrier per stage is safe
#define GRPM 8                // M-tiles per rasterization group

#define A_STAGE_BYTES (BM * 128)   // 16384
#define B_STAGE_BYTES (BN * 128)   // 32768
#define STAGE_BYTES (A_STAGE_BYTES + B_STAGE_BYTES)
#define SMEM_TOTAL (SPIPE * STAGE_BYTES)   // 196608 B

#define MTILES (M_DIM / BM)   // 64
#define NTILES (N_DIM / BN)   // 43

// ---------------- scratch (device globals: sanctioned scratch) ----------------
__device__ float g_wt[(size_t)N_DIM * K_DIM];   // dequantized W^T, tf32-rounded: [N, K]
__device__ float g_ax[(size_t)M_DIM * K_DIM];   // x rounded to tf32: [M, K]

// ---------------- helpers ----------------
__device__ __forceinline__ uint32_t f2tf32(float f) {
    uint32_t r; asm("cvt.rna.tf32.f32 %0, %1;" : "=r"(r) : "f"(f)); return r;
}
__device__ __forceinline__ void cp16(uint32_t saddr, const float* g) {
    asm volatile("cp.async.cg.shared.global [%0], [%1], 16;" :: "r"(saddr), "l"(g));
}
__device__ __forceinline__ void cp_commit() { asm volatile("cp.async.commit_group;" ::: "memory"); }
__device__ __forceinline__ void cp_wait3()  { asm volatile("cp.async.wait_group 3;" ::: "memory"); }
__device__ __forceinline__ uint32_t smem_u32(const void* p) {
    uint32_t a;
    asm("{ .reg .u64 t; cvta.to.shared.u64 t, %1; cvt.u32.u64 %0, t; }" : "=r"(a) : "l"(p));
    return a;
}

// ---------------- prep: round x to tf32 ----------------
extern "C" __global__ void round_a_kernel(const float4* __restrict__ x) {
    size_t i = (size_t)blockIdx.x * blockDim.x + threadIdx.x;
    float4 v = x[i];
    float4 r;
    r.x = __uint_as_float(f2tf32(v.x));
    r.y = __uint_as_float(f2tf32(v.y));
    r.z = __uint_as_float(f2tf32(v.z));
    r.w = __uint_as_float(f2tf32(v.w));
    ((float4*)g_ax)[i] = r;
}

// ---------------- prep: dequant + transpose W -> tf32 [N, K] ----------------
extern "C" __global__ void dequant_wt_kernel(const uint32_t* __restrict__ qweight,
                                             const float* __restrict__ scales,
                                             const uint32_t* __restrict__ qzeros) {
    int n  = blockIdx.x * blockDim.x + threadIdx.x;   // 0..11007
    int kp = blockIdx.y;                              // 0..511 packed k-row (8 k each)
    int g  = kp >> 4;                                 // group index
    uint32_t q  = qweight[(size_t)kp * N_DIM + n];
    float    s  = scales[(size_t)g * N_DIM + n];
    uint32_t zq = qzeros[(size_t)g * NZ_DIM + (n >> 3)];
    float    sz = s * (float)((zq >> ((n & 7) * 4)) & 0xF);
    float w[8];
    #pragma unroll
    for (int j = 0; j < 8; j++)
        w[j] = __uint_as_float(f2tf32(fmaf(s, (float)((q >> (4 * j)) & 0xF), -sz)));
    float4* dst = (float4*)(g_wt + (size_t)n * K_DIM + kp * 8);
    dst[0] = make_float4(w[0], w[1], w[2], w[3]);
    dst[1] = make_float4(w[4], w[5], w[6], w[7]);
}

// ---------------- main GEMM: dense tf32 mma.sync, 128x256 CTA, 64x64 warp ----------------
extern "C" __global__ void __launch_bounds__(256, 1)
qgemm_tf32(float* __restrict__ out) {
    extern __shared__ char smem[];
    uint32_t sb = smem_u32(smem);

    const int t = threadIdx.x;
    const int warp = t >> 5, lane = t & 31;
    const int g8 = lane >> 2, tg = lane & 3;
    const int warp_m = warp >> 2;    // 0..1  -> 64 rows
    const int warp_n = warp & 3;     // 0..3  -> 64 cols

    // grouped-M rasterization: wave working set = GRPM M-tiles x ~18 N-tiles (fits L2)
    const int bid   = blockIdx.x;
    const int group = bid / (GRPM * NTILES);
    const int rem   = bid % (GRPM * NTILES);
    const int m0    = (group * GRPM + (rem % GRPM)) * BM;
    const int n0    = (rem / GRPM) * BN;

    float c[4][8][4];
    #pragma unroll
    for (int i = 0; i < 4; i++)
        #pragma unroll
        for (int j = 0; j < 8; j++)
            #pragma unroll
            for (int k = 0; k < 4; k++) c[i][j][k] = 0.f;

    // ---- cp.async address precompute (SW128 swizzle on 128B rows) ----
    const float* a_g[4]; uint32_t a_s[4];
    #pragma unroll
    for (int i = 0; i < 4; i++) {
        int idx = t + i * 256;            // 0..1023
        int r = idx >> 3, g = idx & 7;    // row 0..127, 16B granule 0..7
        a_g[i] = g_ax + (size_t)(m0 + r) * K_DIM + g * 4;
        a_s[i] = sb + r * 128 + ((g ^ (r & 7)) << 4);
    }
    const float* b_g[8]; uint32_t b_s[8];
    #pragma unroll
    for (int i = 0; i < 8; i++) {
        int idx = t + i * 256;            // 0..2047
        int r = idx >> 3, g = idx & 7;    // row 0..255
        b_g[i] = g_wt + (size_t)(n0 + r) * K_DIM + g * 4;
        b_s[i] = sb + A_STAGE_BYTES + r * 128 + ((g ^ (r & 7)) << 4);
    }

    auto fill = [&](int s) {
        int off = (s & (SPIPE - 1)) * STAGE_BYTES;
        #pragma unroll
        for (int i = 0; i < 4; i++) cp16(a_s[i] + off, a_g[i] + s * BK);
        #pragma unroll
        for (int i = 0; i < 8; i++) cp16(b_s[i] + off, b_g[i] + s * BK);
        cp_commit();
    };

    fill(0); fill(1); fill(2);

    const int axor = g8 << 2;             // swizzle xor for fragment rows (row&7 == g8)

    for (int s = 0; s < NSTAGES; s++) {
        if (s + 3 < NSTAGES) fill(s + 3); else cp_commit();
        cp_wait3();            // group s complete (<=3 groups pending)
        __syncthreads();       // single barrier per stage; SPIPE=4 keeps skew safe

        const uint32_t* A = (const uint32_t*)(smem + (s & (SPIPE - 1)) * STAGE_BYTES);
        const uint32_t* B = A + A_STAGE_BYTES / 4;

        #pragma unroll
        for (int kk = 0; kk < BK; kk += 8) {
            uint32_t af[4][4];
            #pragma unroll
            for (int mi = 0; mi < 4; mi++) {
                int r = warp_m * 64 + mi * 16 + g8;
                const uint32_t* ap = A + r * 32;
                af[mi][0] = ap[(kk + tg) ^ axor];
                af[mi][1] = ap[8 * 32 + ((kk + tg) ^ axor)];
                af[mi][2] = ap[(kk + 4 + tg) ^ axor];
                af[mi][3] = ap[8 * 32 + ((kk + 4 + tg) ^ axor)];
            }
            uint32_t bf[8][2];
            #pragma unroll
            for (int ni = 0; ni < 8; ni++) {
                int r = warp_n * 64 + ni * 8 + g8;
                const uint32_t* bp = B + r * 32;
                bf[ni][0] = bp[(kk + tg) ^ axor];
                bf[ni][1] = bp[(kk + 4 + tg) ^ axor];
            }
            #pragma unroll
            for (int mi = 0; mi < 4; mi++)
                #pragma unroll
                for (int ni = 0; ni < 8; ni++) {
                    asm volatile(
                        "mma.sync.aligned.m16n8k8.row.col.f32.tf32.tf32.f32 "
                        "{%0,%1,%2,%3}, {%4,%5,%6,%7}, {%8,%9}, {%0,%1,%2,%3};"
                        : "+f"(c[mi][ni][0]), "+f"(c[mi][ni][1]),
                          "+f"(c[mi][ni][2]), "+f"(c[mi][ni][3])
                        : "r"(af[mi][0]), "r"(af[mi][1]), "r"(af[mi][2]), "r"(af[mi][3]),
                          "r"(bf[ni][0]), "r"(bf[ni][1]));
                }
        }
    }

    // ---- epilogue ----
    #pragma unroll
    for (int mi = 0; mi < 4; mi++) {
        int row = m0 + warp_m * 64 + mi * 16 + g8;
        float* o0 = out + (size_t)row * N_DIM;
        float* o1 = out + (size_t)(row + 8) * N_DIM;
        #pragma unroll
        for (int ni = 0; ni < 8; ni++) {
            int col = n0 + warp_n * 64 + ni * 8 + 2 * tg;
            *(float2*)(o0 + col) = make_float2(c[mi][ni][0], c[mi][ni][1]);
            *(float2*)(o1 + col) = make_float2(c[mi][ni][2], c[mi][ni][3]);
        }
    }
}

// ---------------- launch ----------------
extern "C" void kernel_launch(void* const* d_in, const int* in_sizes, int n_in,
                              void* d_out, int out_size) {
    const float*    x       = (const float*)d_in[0];
    const uint32_t* qweight = (const uint32_t*)d_in[1];
    const float*    scales  = (const float*)d_in[2];
    const uint32_t* qzeros  = (const uint32_t*)d_in[3];
    float*          out     = (float*)d_out;

    cudaFuncSetAttribute(qgemm_tf32,
                         cudaFuncAttributeMaxDynamicSharedMemorySize, SMEM_TOTAL);

    round_a_kernel<<<(unsigned)((size_t)M_DIM * K_DIM / 4 / 256), 256>>>((const float4*)x);
    dim3 dq_grid(N_DIM / 256, K_DIM / 8);   // (43, 512)
    dequant_wt_kernel<<<dq_grid, 256>>>(qweight, scales, qzeros);
    qgemm_tf32<<<MTILES * NTILES, 256, SMEM_TOTAL>>>(out);   // 2752 CTAs, grouped raster
}